// round 5
// baseline (speedup 1.0000x reference)
#include <cuda_runtime.h>

// ---------------------------------------------------------------------------
// NextVisitTime attention, restructured:
//   scores = us[b] + ts[hour],  us = upt[user] @ K2 (K2 = scale * Wq1 . k),
//   ts = scale*(tq+bq).k,   out = softmax(scores) @ W2 + bu, W2 = v.Wu
// Bulk work: [65536 x 96] @ [96 x 256] fp32 -> FFMA2, 512-thread blocks
// (4 warps/SMSP) for latency hiding.
// ---------------------------------------------------------------------------

#define T_SLOTS 24
#define D_MODEL 256
#define B_BATCH 512
#define S_SEQ   128
#define N_ROWS  (B_BATCH * S_SEQ)   // 65536
#define H_HEADS 4
#define HD      64
#define J_DIM   (H_HEADS * T_SLOTS) // 96

__device__ float g_k  [T_SLOTS * D_MODEL];
__device__ float g_v  [T_SLOTS * D_MODEL];
__device__ float g_tq [T_SLOTS * D_MODEL];
__device__ float g_K2 [D_MODEL * J_DIM];     // scale folded in
__device__ float g_ts [T_SLOTS * J_DIM];
__device__ float g_us [B_BATCH * J_DIM];
__device__ float g_W2 [J_DIM * D_MODEL];

typedef unsigned long long u64;

// ---- f32x2 helpers (FFMA2 only reachable via hand-written PTX) -------------
__device__ __forceinline__ u64 pack_dup(float x) {
    u64 r; asm("mov.b64 %0, {%1, %1};" : "=l"(r) : "f"(x)); return r;
}
__device__ __forceinline__ u64 pack2(float x, float y) {
    u64 r; asm("mov.b64 %0, {%1, %2};" : "=l"(r) : "f"(x), "f"(y)); return r;
}
__device__ __forceinline__ void fma2(u64 &c, u64 a, u64 b) {
    asm("fma.rn.f32x2 %0, %1, %2, %0;" : "+l"(c) : "l"(a), "l"(b));
}
__device__ __forceinline__ float2 unpack2(u64 v) {
    float2 r; asm("mov.b64 {%0, %1}, %2;" : "=f"(r.x), "=f"(r.y) : "l"(v)); return r;
}

// ===========================================================================
// Kernel A: k / v / tq(+bq) rows (t = bx%24, z = bx/24). 72 blocks.
// ===========================================================================
__global__ __launch_bounds__(256) void preA(
    const float* __restrict__ ts_emb,
    const float* __restrict__ Wk, const float* __restrict__ bk,
    const float* __restrict__ Wv, const float* __restrict__ bv,
    const float* __restrict__ Wq, const float* __restrict__ bq)
{
    __shared__ float srow[D_MODEL];
    int bx = blockIdx.x;
    int d  = threadIdx.x;
    int t = bx % 24, z = bx / 24;
    srow[d] = ts_emb[t * D_MODEL + d];
    __syncthreads();
    const float* W; const float* bias; float* outp;
    if (z == 0)      { W = Wk;                     bias = bk; outp = g_k;  }
    else if (z == 1) { W = Wv;                     bias = bv; outp = g_v;  }
    else             { W = Wq + D_MODEL * D_MODEL; bias = bq; outp = g_tq; }
    float a[8];
    a[0] = bias[d];
    #pragma unroll
    for (int i = 1; i < 8; i++) a[i] = 0.f;
    #pragma unroll 4
    for (int c = 0; c < D_MODEL; c += 8) {
        #pragma unroll
        for (int u = 0; u < 8; u++)
            a[u] = fmaf(srow[c + u], W[(c + u) * D_MODEL + d], a[u]);
    }
    outp[t * D_MODEL + d] =
        ((a[0] + a[1]) + (a[2] + a[3])) + ((a[4] + a[5]) + (a[6] + a[7]));
}

// ===========================================================================
// Kernel B:
//   blocks [0,96):    W2 row j
//   blocks [96,192):  K2 col j = bx-96 (thread = c), scale folded
//   blocks [192,201): ts flat (2304 elems)
// ===========================================================================
__global__ __launch_bounds__(256) void preB(const float* __restrict__ Wu,
                                            const float* __restrict__ Wq)
{
    int bx  = blockIdx.x;
    int tid = threadIdx.x;

    if (bx < 96) {                                  // W2[j][d]
        int j = bx;
        int h = j / T_SLOTS, t = j % T_SLOTS;
        __shared__ float vv[HD];
        if (tid < HD) vv[tid] = g_v[t * D_MODEL + h * HD + tid];
        __syncthreads();
        const float* W = Wu + (h * HD) * D_MODEL + tid;
        float a[8];
        #pragma unroll
        for (int i = 0; i < 8; i++) a[i] = 0.f;
        #pragma unroll 2
        for (int e = 0; e < HD; e += 8) {
            #pragma unroll
            for (int u = 0; u < 8; u++)
                a[u] = fmaf(vv[e + u], W[(e + u) * D_MODEL], a[u]);
        }
        g_W2[j * D_MODEL + tid] =
            ((a[0] + a[1]) + (a[2] + a[3])) + ((a[4] + a[5]) + (a[6] + a[7]));
    } else if (bx < 192) {                          // K2[c][j], c = tid
        int j = bx - 96;
        int h = j / T_SLOTS, t = j % T_SLOTS;
        __shared__ __align__(16) float kk[HD];
        if (tid < HD) kk[tid] = g_k[t * D_MODEL + h * HD + tid];
        __syncthreads();
        const float4* wr = (const float4*)(Wq + (size_t)tid * D_MODEL + h * HD);
        const float4* k4 = (const float4*)kk;
        float s0 = 0.f, s1 = 0.f, s2 = 0.f, s3 = 0.f;
        #pragma unroll
        for (int e = 0; e < HD / 4; e++) {
            float4 wv = wr[e], kv = k4[e];
            s0 = fmaf(wv.x, kv.x, s0); s1 = fmaf(wv.y, kv.y, s1);
            s2 = fmaf(wv.z, kv.z, s2); s3 = fmaf(wv.w, kv.w, s3);
        }
        g_K2[tid * J_DIM + j] = ((s0 + s1) + (s2 + s3)) * 0.125f;
    } else {                                        // ts = (tq . k) * scale
        int idx = (bx - 192) * 256 + tid;
        if (idx < T_SLOTS * J_DIM) {
            int th = idx / J_DIM, jj = idx % J_DIM;
            int h = jj / T_SLOTS, t = jj % T_SLOTS;
            const float4* a4 = (const float4*)(g_tq + th * D_MODEL + h * HD);
            const float4* k4 = (const float4*)(g_k  + t  * D_MODEL + h * HD);
            float s0 = 0.f, s1 = 0.f, s2 = 0.f, s3 = 0.f;
            #pragma unroll
            for (int e = 0; e < HD / 4; e++) {
                float4 av = a4[e], kv = k4[e];
                s0 = fmaf(av.x, kv.x, s0); s1 = fmaf(av.y, kv.y, s1);
                s2 = fmaf(av.z, kv.z, s2); s3 = fmaf(av.w, kv.w, s3);
            }
            g_ts[idx] = ((s0 + s1) + (s2 + s3)) * 0.125f;
        }
    }
}

// ===========================================================================
// Kernel C: us[b] = upt[user[b]] @ K2  (8 users per block, 96 threads)
// ===========================================================================
__global__ __launch_bounds__(96) void preC(const int* __restrict__ user,
                                           const float* __restrict__ upt)
{
    __shared__ float srow[8][D_MODEL];
    int b0 = blockIdx.x * 8;
    int j  = threadIdx.x;            // 0..95
    #pragma unroll
    for (int i = 0; i < 8; i++) {
        const float* src = upt + (size_t)__ldg(user + b0 + i) * D_MODEL;
        for (int d = j; d < D_MODEL; d += 96) srow[i][d] = src[d];
    }
    __syncthreads();
    float acc[8];
    #pragma unroll
    for (int i = 0; i < 8; i++) acc[i] = 0.0f;
    #pragma unroll 8
    for (int c = 0; c < D_MODEL; c++) {
        float w = g_K2[c * J_DIM + j];
        #pragma unroll
        for (int i = 0; i < 8; i++) acc[i] = fmaf(srow[i][c], w, acc[i]);
    }
    #pragma unroll
    for (int i = 0; i < 8; i++) g_us[(b0 + i) * J_DIM + j] = acc[i];
}

// ===========================================================================
// Main: 512 threads, 64 rows/block -> softmax + [64x96]@[96x256] FFMA2 GEMM
// SMEM (floats): W2 24576 | attDup 64*97 u64 | ts 2304 | us 96
// ===========================================================================
#define SM_W2       0
#define SM_ATT      24576
#define ATT_PITCH64 97
#define SM_TS       (SM_ATT + 64 * ATT_PITCH64 * 2)   // 36992
#define SM_US       (SM_TS + T_SLOTS * J_DIM)         // 39296
#define SM_FLOATS   (SM_US + J_DIM)                   // 39392
#define SM_BYTES    (SM_FLOATS * 4)                   // 157568

__global__ __launch_bounds__(512, 1) void main_kernel(
    const int* __restrict__ hour, const int* __restrict__ hmask,
    const float* __restrict__ bu, float* __restrict__ out)
{
    extern __shared__ float sm[];
    float* sW2  = sm + SM_W2;
    u64*   sAtt = (u64*)(sm + SM_ATT);
    float* sTs  = sm + SM_TS;
    float* sUs  = sm + SM_US;

    int tid = threadIdx.x;
    int n0  = blockIdx.x * 64;
    int b   = n0 >> 7;            // 64 | 128 -> whole block in one batch row

    // cooperative loads
    {
        const float4* s1 = (const float4*)g_W2;
        float4* d1 = (float4*)sW2;
        #pragma unroll
        for (int i = 0; i < 12; i++) d1[tid + i * 512] = s1[tid + i * 512];
        const float4* s2 = (const float4*)g_ts;
        float4* d2 = (float4*)sTs;
        #pragma unroll
        for (int i = tid; i < (T_SLOTS * J_DIM) / 4; i += 512)  // 576 float4
            d2[i] = s2[i];
        if (tid < J_DIM / 4)
            ((float4*)sUs)[tid] = ((const float4*)(g_us + b * J_DIM))[tid];
    }
    __syncthreads();

    // ---- phase 1: threads [0,256): one per (row, head) masked softmax ----
    if (tid < 256) {
        int r = tid >> 2, h = tid & 3;
        int n = n0 + r;
        int hh = __ldg(hour + n);
        int msk[T_SLOTS];
        const int4* mp = (const int4*)(hmask + (size_t)n * T_SLOTS);
        #pragma unroll
        for (int i = 0; i < 6; i++) {
            int4 q = mp[i];
            msk[4*i] = q.x; msk[4*i+1] = q.y; msk[4*i+2] = q.z; msk[4*i+3] = q.w;
        }
        const float* usb = sUs + h * T_SLOTS;
        const float* tsb = sTs + hh * J_DIM + h * T_SLOTS;
        float sc[T_SLOTS];
        float mx = -3.0e38f;
        #pragma unroll
        for (int t = 0; t < T_SLOTS; t++) {
            sc[t] = msk[t] ? -1e9f : (usb[t] + tsb[t]);
            mx = fmaxf(mx, sc[t]);
        }
        float s = 0.0f;
        #pragma unroll
        for (int t = 0; t < T_SLOTS; t++) {
            float e = __expf(sc[t] - mx);
            sc[t] = e; s += e;
        }
        float inv = 1.0f / s;
        u64* ar = sAtt + r * ATT_PITCH64 + h * T_SLOTS;
        #pragma unroll
        for (int t = 0; t < T_SLOTS; t++) ar[t] = pack_dup(sc[t] * inv);
    }
    __syncthreads();

    // ---- phase 2: [64 x 96] @ [96 x 256], 2 rows x 16 cols per thread ----
    // Thread (rg,cg): rows rg*2..+1; u128 weight cols {cg + 16i : i<4}.
    // In-warp: lanes 0-15 stream 16 consecutive u128, lanes 16-31 broadcast
    // the same; att LDS.64 is a 2-address broadcast. Conflict-free.
    int rg = tid >> 4, cg = tid & 15;
    int r0 = rg * 2;
    u64 acc[2][4][2];
    #pragma unroll
    for (int i = 0; i < 4; i++) {
        float4 bv = __ldg((const float4*)bu + cg + 16 * i);
        u64 blo = pack2(bv.x, bv.y), bhi = pack2(bv.z, bv.w);
        #pragma unroll
        for (int rr = 0; rr < 2; rr++) { acc[rr][i][0] = blo; acc[rr][i][1] = bhi; }
    }
    const ulonglong2* w2p = (const ulonglong2*)sW2;
    const u64* ap = sAtt + r0 * ATT_PITCH64;
    #pragma unroll 4
    for (int j = 0; j < J_DIM; j++) {
        ulonglong2 w[4];
        #pragma unroll
        for (int i = 0; i < 4; i++) w[i] = w2p[j * (D_MODEL / 4) + cg + 16 * i];
        #pragma unroll
        for (int rr = 0; rr < 2; rr++) {
            u64 a = ap[rr * ATT_PITCH64 + j];
            #pragma unroll
            for (int i = 0; i < 4; i++) {
                fma2(acc[rr][i][0], a, w[i].x);
                fma2(acc[rr][i][1], a, w[i].y);
            }
        }
    }
    #pragma unroll
    for (int rr = 0; rr < 2; rr++) {
        float4* orow = (float4*)(out + (size_t)(n0 + r0 + rr) * D_MODEL);
        #pragma unroll
        for (int i = 0; i < 4; i++) {
            float2 lo = unpack2(acc[rr][i][0]);
            float2 hi = unpack2(acc[rr][i][1]);
            orow[cg + 16 * i] = make_float4(lo.x, lo.y, hi.x, hi.y);
        }
    }
}

extern "C" void kernel_launch(void* const* d_in, const int* in_sizes, int n_in,
                              void* d_out, int out_size) {
    const float* ts_emb = (const float*)d_in[0];
    const int*   user   = (const int*)  d_in[1];
    const int*   hour   = (const int*)  d_in[2];
    const int*   hmask  = (const int*)  d_in[3];
    const float* upt    = (const float*)d_in[4];
    const float* Wq     = (const float*)d_in[5];
    const float* bq     = (const float*)d_in[6];
    const float* Wk     = (const float*)d_in[7];
    const float* bk     = (const float*)d_in[8];
    const float* Wv     = (const float*)d_in[9];
    const float* bv     = (const float*)d_in[10];
    const float* Wu     = (const float*)d_in[11];
    const float* bu     = (const float*)d_in[12];
    float* out = (float*)d_out;

    preA<<<72, 256>>>(ts_emb, Wk, bk, Wv, bv, Wq, bq);
    preB<<<201, 256>>>(Wu, Wq);
    preC<<<B_BATCH / 8, 96>>>(user, upt);

    cudaFuncSetAttribute(main_kernel, cudaFuncAttributeMaxDynamicSharedMemorySize, SM_BYTES);
    main_kernel<<<N_ROWS / 64, 512, SM_BYTES>>>(hour, hmask, bu, out);
}